// round 10
// baseline (speedup 1.0000x reference)
#include <cuda_runtime.h>

#define N_NODES 500000
#define N_EDGES 16000000

#define NODE_TB 256
#define NODE_GRID 1024      // k_node blocks
#define NPART NODE_GRID

// ---- device scratch (no allocations allowed; __device__ statics only) ----
__device__ int    g_idx64;            // 1 if edge_index is int64, 0 if int32
__device__ float  g_deg[N_NODES];     // sum of incoming edge weights (+1 self-loop added at read)
__device__ float  g_dis[N_NODES];     // rsqrt(deg)
__device__ float  g_q[N_NODES];       // dis * x
__device__ float  g_acc[N_NODES];     // sum_{e->d} ew * q[src]
__device__ float  g_u[N_NODES];       // sum_{e from s} ew * dis[dst]
__device__ double g_part0[NPART];     // per-block partial sums, channel 0
__device__ double g_part1[NPART];     // per-block partial sums, channel 1

// ---------------------------------------------------------------- dtype detect (1 warp)
__global__ void k_detect(const int* __restrict__ eiw) {
    if (threadIdx.x == 0) {
        int all_zero = 1;
        #pragma unroll
        for (int k = 0; k < 8; k++) all_zero &= (eiw[2 * k + 1] == 0);
        g_idx64 = all_zero;
    }
}

// ---------------------------------------------------------------- index fetch helpers
__device__ __forceinline__ void load_idx4(const void* ei, int row, int t,
                                          int& i0, int& i1, int& i2, int& i3) {
    if (!g_idx64) {
        int4 v = ((const int4*)ei)[(size_t)row * (N_EDGES / 4) + t];
        i0 = v.x; i1 = v.y; i2 = v.z; i3 = v.w;
    } else {
        const longlong2* p = (const longlong2*)((const long long*)ei + (size_t)row * N_EDGES);
        longlong2 a = p[2 * t];
        longlong2 b = p[2 * t + 1];
        i0 = (int)a.x; i1 = (int)a.y; i2 = (int)b.x; i3 = (int)b.y;
    }
}

__device__ __forceinline__ int load_idx1(const void* ei, int row, int t) {
    if (!g_idx64) {
        return ((const int*)ei)[(size_t)row * N_EDGES + t];
    } else {
        return (int)((const long long*)ei)[(size_t)row * N_EDGES + t];
    }
}

// ---------------------------------------------------------------- pass 1: degree (4 edges/thread)
__global__ void k_deg(const void* __restrict__ ei, const float4* __restrict__ ew4) {
    int t = blockIdx.x * blockDim.x + threadIdx.x;   // t < N_EDGES/4 exactly
    float4 w = ew4[t];
    int d0, d1, d2, d3;
    load_idx4(ei, 1, t, d0, d1, d2, d3);
    if ((unsigned)d0 < N_NODES) atomicAdd(&g_deg[d0], w.x);
    if ((unsigned)d1 < N_NODES) atomicAdd(&g_deg[d1], w.y);
    if ((unsigned)d2 < N_NODES) atomicAdd(&g_deg[d2], w.z);
    if ((unsigned)d3 < N_NODES) atomicAdd(&g_deg[d3], w.w);
}

// ---------------------------------------------------------------- node: dis, q
__global__ void k_dis(const float* __restrict__ x) {
    int i = blockIdx.x * blockDim.x + threadIdx.x;
    if (i < N_NODES) {
        float s = rsqrtf(g_deg[i] + 1.0f);   // +1 = self-loop weight (deg starts at 0)
        g_dis[i] = s;
        g_q[i]   = s * x[i];
    }
}

// ---------------------------------------------------------------- pass 2 (fused, 1 edge/thread):
//   acc[d] += ew * q[s]        (layer-1 aggregation)
//   u[s]   += ew * dis[d]      (edge coefficient of final sum)
// 1 edge/thread keeps the per-thread memory-op count small (7) to avoid
// cross-CTA L1tex-queue contention (the R5 failure mode at 19 memops).
__global__ void k_msgu(const void* __restrict__ ei, const float* __restrict__ ew) {
    int t = blockIdx.x * blockDim.x + threadIdx.x;   // t < N_EDGES exactly
    float w = ew[t];
    int s = load_idx1(ei, 0, t);
    int d = load_idx1(ei, 1, t);
    bool vs = (unsigned)s < N_NODES;
    bool vd = (unsigned)d < N_NODES;
    float q = vs ? g_q[s]   : 0.0f;
    float c = vd ? g_dis[d] : 0.0f;
    if (vd) atomicAdd(&g_acc[d], w * q);
    if (vs) atomicAdd(&g_u[s],   w * c);
}

// ---------------------------------------------------------------- shared-mem double tree reduce
__device__ __forceinline__ void block_reduce_store(float a0, float a1, int slot) {
    __shared__ double sm0[NODE_TB], sm1[NODE_TB];
    int t = threadIdx.x;
    sm0[t] = (double)a0;
    sm1[t] = (double)a1;
    __syncthreads();
    #pragma unroll
    for (int s = NODE_TB / 2; s > 0; s >>= 1) {
        if (t < s) { sm0[t] += sm0[t + s]; sm1[t] += sm1[t + s]; }
        __syncthreads();
    }
    if (t == 0) { g_part0[slot] = sm0[0]; g_part1[slot] = sm1[0]; }
}

// ---------------------------------------------------------------- node: MLP + full per-node contribution
// contribution of node i to s[c]:  h2[i,c] * (1/deg_i + dis_i * u_i)
__global__ void k_node(const float* __restrict__ x, const float* __restrict__ W1,
                       const float* __restrict__ b1, const float* __restrict__ W2) {
    __shared__ float sW1[16], sb1[16], sW2[32];
    int t = threadIdx.x;
    if (t < 16) { sW1[t] = W1[t]; sb1[t] = b1[t]; }
    if (t < 32) sW2[t] = W2[t];
    __syncthreads();

    float a0 = 0.0f, a1 = 0.0f;
    int stride = gridDim.x * blockDim.x;
    for (int i = blockIdx.x * blockDim.x + t; i < N_NODES; i += stride) {
        float dis = g_dis[i];
        float inv = dis * dis;                     // 1/deg
        float agg = dis * g_acc[i] + x[i] * inv;   // layer-1 scalar aggregate
        float h0 = 0.0f, h1 = 0.0f;
        #pragma unroll
        for (int j = 0; j < 16; j++) {
            float h = fmaxf(fmaf(sW1[j], agg, sb1[j]), 0.0f);
            h0 = fmaf(h, sW2[2 * j],     h0);
            h1 = fmaf(h, sW2[2 * j + 1], h1);
        }
        float coef = fmaf(dis, g_u[i], inv);       // self + edge terms of final sum
        a0 = fmaf(coef, h0, a0);
        a1 = fmaf(coef, h1, a1);
    }
    block_reduce_store(a0, a1, blockIdx.x);
}

// ---------------------------------------------------------------- final: reduce partials, bias, softmax
__global__ void k_final(const float* __restrict__ b2, float* __restrict__ out) {
    __shared__ double sm0[256], sm1[256];
    int t = threadIdx.x;
    double s0 = 0.0, s1 = 0.0;
    for (int k = t; k < NPART; k += 256) { s0 += g_part0[k]; s1 += g_part1[k]; }
    sm0[t] = s0; sm1[t] = s1;
    __syncthreads();
    #pragma unroll
    for (int s = 128; s > 0; s >>= 1) {
        if (t < s) { sm0[t] += sm0[t + s]; sm1[t] += sm1[t + s]; }
        __syncthreads();
    }
    if (t == 0) {
        double v0 = sm0[0] + (double)N_NODES * (double)b2[0];
        double v1 = sm1[0] + (double)N_NODES * (double)b2[1];
        double m  = fmax(v0, v1);
        double e0 = exp(v0 - m), e1 = exp(v1 - m);
        double den = e0 + e1;
        out[0] = (float)(e0 / den);
        out[1] = (float)(e1 / den);
    }
}

// ---------------------------------------------------------------- launch
extern "C" void kernel_launch(void* const* d_in, const int* in_sizes, int n_in,
                              void* d_out, int out_size) {
    const float* x  = (const float*)d_in[0];
    const void*  ei = d_in[1];                 // int32 OR int64, detected on device
    const float* ew = (const float*)d_in[2];
    const float* W1 = (const float*)d_in[3];
    const float* b1 = (const float*)d_in[4];
    const float* W2 = (const float*)d_in[5];
    const float* b2 = (const float*)d_in[6];

    const int TB = 256;
    const int nodeBlocks  = (N_NODES + TB - 1) / TB;        // 1954
    const int edge4Blocks = (N_EDGES / 4) / TB;             // 15625 exact
    const int edge1Blocks = N_EDGES / TB;                   // 62500 exact

    // Zero the scatter targets with bulk memsets (graph-capturable, no alloc).
    // Also warms the scratch lines in L2 ahead of the atomic passes.
    void *p_deg = nullptr, *p_acc = nullptr, *p_u = nullptr;
    cudaGetSymbolAddress(&p_deg, g_deg);
    cudaGetSymbolAddress(&p_acc, g_acc);
    cudaGetSymbolAddress(&p_u,   g_u);
    cudaMemsetAsync(p_deg, 0, N_NODES * sizeof(float));
    cudaMemsetAsync(p_acc, 0, N_NODES * sizeof(float));
    cudaMemsetAsync(p_u,   0, N_NODES * sizeof(float));

    k_detect<<<1, 32>>>((const int*)ei);
    k_deg   <<<edge4Blocks, TB>>>(ei, (const float4*)ew);
    k_dis   <<<nodeBlocks, TB>>>(x);
    k_msgu  <<<edge1Blocks, TB>>>(ei, ew);
    k_node  <<<NODE_GRID, NODE_TB>>>(x, W1, b1, W2);
    k_final <<<1, 256>>>(b2, (float*)d_out);
}

// round 11
// speedup vs baseline: 1.0150x; 1.0150x over previous
#include <cuda_runtime.h>

#define N_NODES 500000
#define N_EDGES 16000000

#define NODE_TB 256
#define NODE_GRID 1024      // k_node blocks
#define NPART NODE_GRID

// ---- device scratch (no allocations allowed; __device__ statics only) ----
__device__ int    g_idx64;            // 1 if edge_index is int64, 0 if int32
__device__ float  g_deg[N_NODES];     // 1 + sum of incoming edge weights
__device__ float  g_dis[N_NODES];     // rsqrt(deg)
__device__ float  g_q[N_NODES];       // dis * x
__device__ float  g_acc[N_NODES];     // sum_{e->d} ew * q[src]
__device__ float  g_u[N_NODES];       // sum_{e from s} ew * dis[dst]
__device__ double g_part0[NPART];     // per-block partial sums, channel 0
__device__ double g_part1[NPART];     // per-block partial sums, channel 1

// ---------------------------------------------------------------- dtype detect (1 warp)
__global__ void k_detect(const int* __restrict__ eiw) {
    if (threadIdx.x == 0) {
        int all_zero = 1;
        #pragma unroll
        for (int k = 0; k < 8; k++) all_zero &= (eiw[2 * k + 1] == 0);
        g_idx64 = all_zero;
    }
}

// ---------------------------------------------------------------- index fetch helpers
__device__ __forceinline__ void load_idx4(const void* ei, int row, int t,
                                          int& i0, int& i1, int& i2, int& i3) {
    if (!g_idx64) {
        int4 v = ((const int4*)ei)[(size_t)row * (N_EDGES / 4) + t];
        i0 = v.x; i1 = v.y; i2 = v.z; i3 = v.w;
    } else {
        const longlong2* p = (const longlong2*)((const long long*)ei + (size_t)row * N_EDGES);
        longlong2 a = p[2 * t];
        longlong2 b = p[2 * t + 1];
        i0 = (int)a.x; i1 = (int)a.y; i2 = (int)b.x; i3 = (int)b.y;
    }
}

__device__ __forceinline__ void load_idx2(const void* ei, int row, int t,
                                          int& i0, int& i1) {
    if (!g_idx64) {
        int2 v = ((const int2*)ei)[(size_t)row * (N_EDGES / 2) + t];
        i0 = v.x; i1 = v.y;
    } else {
        longlong2 v = ((const longlong2*)((const long long*)ei + (size_t)row * N_EDGES))[t];
        i0 = (int)v.x; i1 = (int)v.y;
    }
}

// ---------------------------------------------------------------- init (also warms scratch lines in L2)
__global__ void k_init() {
    int i = blockIdx.x * blockDim.x + threadIdx.x;
    if (i < N_NODES) { g_deg[i] = 1.0f; g_acc[i] = 0.0f; g_u[i] = 0.0f; }
}

// ---------------------------------------------------------------- pass 1: degree (4 edges/thread)
__global__ void k_deg(const void* __restrict__ ei, const float4* __restrict__ ew4) {
    int t = blockIdx.x * blockDim.x + threadIdx.x;   // t < N_EDGES/4 exactly
    float4 w = ew4[t];
    int d0, d1, d2, d3;
    load_idx4(ei, 1, t, d0, d1, d2, d3);
    if ((unsigned)d0 < N_NODES) atomicAdd(&g_deg[d0], w.x);
    if ((unsigned)d1 < N_NODES) atomicAdd(&g_deg[d1], w.y);
    if ((unsigned)d2 < N_NODES) atomicAdd(&g_deg[d2], w.z);
    if ((unsigned)d3 < N_NODES) atomicAdd(&g_deg[d3], w.w);
}

// ---------------------------------------------------------------- node: dis, q
__global__ void k_dis(const float* __restrict__ x) {
    int i = blockIdx.x * blockDim.x + threadIdx.x;
    if (i < N_NODES) {
        float s = rsqrtf(g_deg[i]);     // deg >= 1 (self-loop weight 1, set by k_init)
        g_dis[i] = s;
        g_q[i]   = s * x[i];
    }
}

// ---------------------------------------------------------------- pass 2 (fused, 2 edges/thread):
//   acc[d] += ew * q[s]        (layer-1 aggregation)
//   u[s]   += ew * dis[d]      (edge coefficient of final sum)
// 11 memops/thread — same count as the R4 k_msg body that measured at the
// lane floor; halves stream-load requests vs the 1-edge/thread version.
__global__ void k_msgu(const void* __restrict__ ei, const float2* __restrict__ ew2) {
    int t = blockIdx.x * blockDim.x + threadIdx.x;   // t < N_EDGES/2 exactly
    float2 w = ew2[t];
    int s0, s1, d0, d1;
    load_idx2(ei, 0, t, s0, s1);
    load_idx2(ei, 1, t, d0, d1);
    bool vs0 = (unsigned)s0 < N_NODES, vs1 = (unsigned)s1 < N_NODES;
    bool vd0 = (unsigned)d0 < N_NODES, vd1 = (unsigned)d1 < N_NODES;
    float q0 = vs0 ? g_q[s0]   : 0.0f;
    float q1 = vs1 ? g_q[s1]   : 0.0f;
    float c0 = vd0 ? g_dis[d0] : 0.0f;
    float c1 = vd1 ? g_dis[d1] : 0.0f;
    if (vd0) atomicAdd(&g_acc[d0], w.x * q0);
    if (vd1) atomicAdd(&g_acc[d1], w.y * q1);
    if (vs0) atomicAdd(&g_u[s0],   w.x * c0);
    if (vs1) atomicAdd(&g_u[s1],   w.y * c1);
}

// ---------------------------------------------------------------- shared-mem double tree reduce
__device__ __forceinline__ void block_reduce_store(float a0, float a1, int slot) {
    __shared__ double sm0[NODE_TB], sm1[NODE_TB];
    int t = threadIdx.x;
    sm0[t] = (double)a0;
    sm1[t] = (double)a1;
    __syncthreads();
    #pragma unroll
    for (int s = NODE_TB / 2; s > 0; s >>= 1) {
        if (t < s) { sm0[t] += sm0[t + s]; sm1[t] += sm1[t + s]; }
        __syncthreads();
    }
    if (t == 0) { g_part0[slot] = sm0[0]; g_part1[slot] = sm1[0]; }
}

// ---------------------------------------------------------------- node: MLP + full per-node contribution
// contribution of node i to s[c]:  h2[i,c] * (1/deg_i + dis_i * u_i)
__global__ void k_node(const float* __restrict__ x, const float* __restrict__ W1,
                       const float* __restrict__ b1, const float* __restrict__ W2) {
    __shared__ float sW1[16], sb1[16], sW2[32];
    int t = threadIdx.x;
    if (t < 16) { sW1[t] = W1[t]; sb1[t] = b1[t]; }
    if (t < 32) sW2[t] = W2[t];
    __syncthreads();

    float a0 = 0.0f, a1 = 0.0f;
    int stride = gridDim.x * blockDim.x;
    for (int i = blockIdx.x * blockDim.x + t; i < N_NODES; i += stride) {
        float dis = g_dis[i];
        float inv = dis * dis;                     // 1/deg
        float agg = dis * g_acc[i] + x[i] * inv;   // layer-1 scalar aggregate
        float h0 = 0.0f, h1 = 0.0f;
        #pragma unroll
        for (int j = 0; j < 16; j++) {
            float h = fmaxf(fmaf(sW1[j], agg, sb1[j]), 0.0f);
            h0 = fmaf(h, sW2[2 * j],     h0);
            h1 = fmaf(h, sW2[2 * j + 1], h1);
        }
        float coef = fmaf(dis, g_u[i], inv);       // self + edge terms of final sum
        a0 = fmaf(coef, h0, a0);
        a1 = fmaf(coef, h1, a1);
    }
    block_reduce_store(a0, a1, blockIdx.x);
}

// ---------------------------------------------------------------- final: reduce partials, bias, softmax
__global__ void k_final(const float* __restrict__ b2, float* __restrict__ out) {
    __shared__ double sm0[256], sm1[256];
    int t = threadIdx.x;
    double s0 = 0.0, s1 = 0.0;
    for (int k = t; k < NPART; k += 256) { s0 += g_part0[k]; s1 += g_part1[k]; }
    sm0[t] = s0; sm1[t] = s1;
    __syncthreads();
    #pragma unroll
    for (int s = 128; s > 0; s >>= 1) {
        if (t < s) { sm0[t] += sm0[t + s]; sm1[t] += sm1[t + s]; }
        __syncthreads();
    }
    if (t == 0) {
        double v0 = sm0[0] + (double)N_NODES * (double)b2[0];
        double v1 = sm1[0] + (double)N_NODES * (double)b2[1];
        double m  = fmax(v0, v1);
        double e0 = exp(v0 - m), e1 = exp(v1 - m);
        double den = e0 + e1;
        out[0] = (float)(e0 / den);
        out[1] = (float)(e1 / den);
    }
}

// ---------------------------------------------------------------- launch
extern "C" void kernel_launch(void* const* d_in, const int* in_sizes, int n_in,
                              void* d_out, int out_size) {
    const float* x  = (const float*)d_in[0];
    const void*  ei = d_in[1];                 // int32 OR int64, detected on device
    const float* ew = (const float*)d_in[2];
    const float* W1 = (const float*)d_in[3];
    const float* b1 = (const float*)d_in[4];
    const float* W2 = (const float*)d_in[5];
    const float* b2 = (const float*)d_in[6];

    const int TB = 256;
    const int nodeBlocks  = (N_NODES + TB - 1) / TB;        // 1954
    const int edge4Blocks = (N_EDGES / 4) / TB;             // 15625 exact
    const int edge2Blocks = (N_EDGES / 2) / TB;             // 31250 exact

    k_detect<<<1, 32>>>((const int*)ei);
    k_init  <<<nodeBlocks, TB>>>();
    k_deg   <<<edge4Blocks, TB>>>(ei, (const float4*)ew);
    k_dis   <<<nodeBlocks, TB>>>(x);
    k_msgu  <<<edge2Blocks, TB>>>(ei, (const float2*)ew);
    k_node  <<<NODE_GRID, NODE_TB>>>(x, W1, b1, W2);
    k_final <<<1, 256>>>(b2, (float*)d_out);
}

// round 12
// speedup vs baseline: 1.0153x; 1.0003x over previous
#include <cuda_runtime.h>

#define N_NODES 500000
#define N_EDGES 16000000

#define NODE_TB 256
#define NODE_GRID 1024      // k_node blocks
#define NPART NODE_GRID

// ---- device scratch (no allocations allowed; __device__ statics only) ----
__device__ int    g_idx64;            // 1 if edge_index is int64, 0 if int32
__device__ float  g_deg[N_NODES];     // 1 + sum of incoming edge weights
__device__ float  g_dis[N_NODES];     // rsqrt(deg)
__device__ float  g_q[N_NODES];       // dis * x
__device__ float  g_acc[N_NODES];     // sum_{e->d} ew * q[src]
__device__ float  g_u[N_NODES];       // sum_{e from s} ew * dis[dst]
__device__ double g_part0[NPART];     // per-block partial sums, channel 0
__device__ double g_part1[NPART];     // per-block partial sums, channel 1

// ---------------------------------------------------------------- dtype detect (1 warp)
__global__ void k_detect(const int* __restrict__ eiw) {
    if (threadIdx.x == 0) {
        int all_zero = 1;
        #pragma unroll
        for (int k = 0; k < 8; k++) all_zero &= (eiw[2 * k + 1] == 0);
        g_idx64 = all_zero;
    }
}

// ---------------------------------------------------------------- index fetch helpers
__device__ __forceinline__ void load_idx4(const void* ei, int row, int t,
                                          int& i0, int& i1, int& i2, int& i3) {
    if (!g_idx64) {
        int4 v = ((const int4*)ei)[(size_t)row * (N_EDGES / 4) + t];
        i0 = v.x; i1 = v.y; i2 = v.z; i3 = v.w;
    } else {
        const longlong2* p = (const longlong2*)((const long long*)ei + (size_t)row * N_EDGES);
        longlong2 a = p[2 * t];
        longlong2 b = p[2 * t + 1];
        i0 = (int)a.x; i1 = (int)a.y; i2 = (int)b.x; i3 = (int)b.y;
    }
}

__device__ __forceinline__ void load_idx2(const void* ei, int row, int t,
                                          int& i0, int& i1) {
    if (!g_idx64) {
        int2 v = ((const int2*)ei)[(size_t)row * (N_EDGES / 2) + t];
        i0 = v.x; i1 = v.y;
    } else {
        longlong2 v = ((const longlong2*)((const long long*)ei + (size_t)row * N_EDGES))[t];
        i0 = (int)v.x; i1 = (int)v.y;
    }
}

// ---------------------------------------------------------------- init: deg only (warms deg lines in L2)
__global__ void k_init() {
    int i = blockIdx.x * blockDim.x + threadIdx.x;
    if (i < N_NODES) g_deg[i] = 1.0f;
}

// ---------------------------------------------------------------- pass 1: degree (4 edges/thread)
__global__ void k_deg(const void* __restrict__ ei, const float4* __restrict__ ew4) {
    int t = blockIdx.x * blockDim.x + threadIdx.x;   // t < N_EDGES/4 exactly
    float4 w = ew4[t];
    int d0, d1, d2, d3;
    load_idx4(ei, 1, t, d0, d1, d2, d3);
    if ((unsigned)d0 < N_NODES) atomicAdd(&g_deg[d0], w.x);
    if ((unsigned)d1 < N_NODES) atomicAdd(&g_deg[d1], w.y);
    if ((unsigned)d2 < N_NODES) atomicAdd(&g_deg[d2], w.z);
    if ((unsigned)d3 < N_NODES) atomicAdd(&g_deg[d3], w.w);
}

// ---------------------------------------------------------------- node: dis, q (+ zero acc,u right before k_msgu needs them)
__global__ void k_dis(const float* __restrict__ x) {
    int i = blockIdx.x * blockDim.x + threadIdx.x;
    if (i < N_NODES) {
        float s = rsqrtf(g_deg[i]);     // deg >= 1 (self-loop weight 1, set by k_init)
        g_dis[i] = s;
        g_q[i]   = s * x[i];
        g_acc[i] = 0.0f;                // zero + L2-warm the scatter targets
        g_u[i]   = 0.0f;
    }
}

// ---------------------------------------------------------------- pass 2 (fused, 2 edges/thread):
//   acc[d] += ew * q[s]        (layer-1 aggregation)
//   u[s]   += ew * dis[d]      (edge coefficient of final sum)
// 11 memops/thread — measured at the lane floor (R4/R11); 19 collapses (R5).
__global__ void k_msgu(const void* __restrict__ ei, const float2* __restrict__ ew2) {
    int t = blockIdx.x * blockDim.x + threadIdx.x;   // t < N_EDGES/2 exactly
    float2 w = ew2[t];
    int s0, s1, d0, d1;
    load_idx2(ei, 0, t, s0, s1);
    load_idx2(ei, 1, t, d0, d1);
    bool vs0 = (unsigned)s0 < N_NODES, vs1 = (unsigned)s1 < N_NODES;
    bool vd0 = (unsigned)d0 < N_NODES, vd1 = (unsigned)d1 < N_NODES;
    float q0 = vs0 ? g_q[s0]   : 0.0f;
    float q1 = vs1 ? g_q[s1]   : 0.0f;
    float c0 = vd0 ? g_dis[d0] : 0.0f;
    float c1 = vd1 ? g_dis[d1] : 0.0f;
    if (vd0) atomicAdd(&g_acc[d0], w.x * q0);
    if (vd1) atomicAdd(&g_acc[d1], w.y * q1);
    if (vs0) atomicAdd(&g_u[s0],   w.x * c0);
    if (vs1) atomicAdd(&g_u[s1],   w.y * c1);
}

// ---------------------------------------------------------------- shared-mem double tree reduce
__device__ __forceinline__ void block_reduce_store(float a0, float a1, int slot) {
    __shared__ double sm0[NODE_TB], sm1[NODE_TB];
    int t = threadIdx.x;
    sm0[t] = (double)a0;
    sm1[t] = (double)a1;
    __syncthreads();
    #pragma unroll
    for (int s = NODE_TB / 2; s > 0; s >>= 1) {
        if (t < s) { sm0[t] += sm0[t + s]; sm1[t] += sm1[t + s]; }
        __syncthreads();
    }
    if (t == 0) { g_part0[slot] = sm0[0]; g_part1[slot] = sm1[0]; }
}

// ---------------------------------------------------------------- node: MLP + full per-node contribution
// contribution of node i to s[c]:  h2[i,c] * (1/deg_i + dis_i * u_i)
__global__ void k_node(const float* __restrict__ x, const float* __restrict__ W1,
                       const float* __restrict__ b1, const float* __restrict__ W2) {
    __shared__ float sW1[16], sb1[16], sW2[32];
    int t = threadIdx.x;
    if (t < 16) { sW1[t] = W1[t]; sb1[t] = b1[t]; }
    if (t < 32) sW2[t] = W2[t];
    __syncthreads();

    float a0 = 0.0f, a1 = 0.0f;
    int stride = gridDim.x * blockDim.x;
    for (int i = blockIdx.x * blockDim.x + t; i < N_NODES; i += stride) {
        float dis = g_dis[i];
        float inv = dis * dis;                     // 1/deg
        float agg = dis * g_acc[i] + x[i] * inv;   // layer-1 scalar aggregate
        float h0 = 0.0f, h1 = 0.0f;
        #pragma unroll
        for (int j = 0; j < 16; j++) {
            float h = fmaxf(fmaf(sW1[j], agg, sb1[j]), 0.0f);
            h0 = fmaf(h, sW2[2 * j],     h0);
            h1 = fmaf(h, sW2[2 * j + 1], h1);
        }
        float coef = fmaf(dis, g_u[i], inv);       // self + edge terms of final sum
        a0 = fmaf(coef, h0, a0);
        a1 = fmaf(coef, h1, a1);
    }
    block_reduce_store(a0, a1, blockIdx.x);
}

// ---------------------------------------------------------------- final: reduce partials, bias, softmax
__global__ void k_final(const float* __restrict__ b2, float* __restrict__ out) {
    __shared__ double sm0[256], sm1[256];
    int t = threadIdx.x;
    double s0 = 0.0, s1 = 0.0;
    for (int k = t; k < NPART; k += 256) { s0 += g_part0[k]; s1 += g_part1[k]; }
    sm0[t] = s0; sm1[t] = s1;
    __syncthreads();
    #pragma unroll
    for (int s = 128; s > 0; s >>= 1) {
        if (t < s) { sm0[t] += sm0[t + s]; sm1[t] += sm1[t + s]; }
        __syncthreads();
    }
    if (t == 0) {
        double v0 = sm0[0] + (double)N_NODES * (double)b2[0];
        double v1 = sm1[0] + (double)N_NODES * (double)b2[1];
        double m  = fmax(v0, v1);
        double e0 = exp(v0 - m), e1 = exp(v1 - m);
        double den = e0 + e1;
        out[0] = (float)(e0 / den);
        out[1] = (float)(e1 / den);
    }
}

// ---------------------------------------------------------------- launch
extern "C" void kernel_launch(void* const* d_in, const int* in_sizes, int n_in,
                              void* d_out, int out_size) {
    const float* x  = (const float*)d_in[0];
    const void*  ei = d_in[1];                 // int32 OR int64, detected on device
    const float* ew = (const float*)d_in[2];
    const float* W1 = (const float*)d_in[3];
    const float* b1 = (const float*)d_in[4];
    const float* W2 = (const float*)d_in[5];
    const float* b2 = (const float*)d_in[6];

    const int TB = 256;
    const int nodeBlocks  = (N_NODES + TB - 1) / TB;        // 1954
    const int edge4Blocks = (N_EDGES / 4) / TB;             // 15625 exact
    const int edge2Blocks = (N_EDGES / 2) / TB;             // 31250 exact

    k_detect<<<1, 32>>>((const int*)ei);
    k_init  <<<nodeBlocks, TB>>>();
    k_deg   <<<edge4Blocks, TB>>>(ei, (const float4*)ew);
    k_dis   <<<nodeBlocks, TB>>>(x);
    k_msgu  <<<edge2Blocks, TB>>>(ei, (const float2*)ew);
    k_node  <<<NODE_GRID, NODE_TB>>>(x, W1, b1, W2);
    k_final <<<1, 256>>>(b2, (float*)d_out);
}

// round 13
// speedup vs baseline: 1.0168x; 1.0015x over previous
#include <cuda_runtime.h>

#define N_NODES 500000
#define N_EDGES 16000000

#define NODE_TB 256
#define NODE_GRID 1024      // k_node blocks
#define NPART NODE_GRID

// ---- device scratch (no allocations allowed; __device__ statics only) ----
__device__ int    g_idx64;            // 1 if edge_index is int64, 0 if int32
__device__ float  g_deg[N_NODES];     // 1 + sum of incoming edge weights
__device__ float  g_dis[N_NODES];     // rsqrt(deg)
__device__ float  g_q[N_NODES];       // dis * x
__device__ float  g_acc[N_NODES];     // sum_{e->d} ew * q[src]
__device__ float  g_u[N_NODES];       // sum_{e from s} ew * dis[dst]
__device__ double g_part0[NPART];     // per-block partial sums, channel 0
__device__ double g_part1[NPART];     // per-block partial sums, channel 1

// ---------------------------------------------------------------- dtype detect (1 warp)
__global__ void k_detect(const int* __restrict__ eiw) {
    if (threadIdx.x == 0) {
        int all_zero = 1;
        #pragma unroll
        for (int k = 0; k < 8; k++) all_zero &= (eiw[2 * k + 1] == 0);
        g_idx64 = all_zero;
    }
}

// ---------------------------------------------------------------- index fetch helpers
__device__ __forceinline__ void load_idx4(const void* ei, int row, int t,
                                          int& i0, int& i1, int& i2, int& i3) {
    if (!g_idx64) {
        int4 v = ((const int4*)ei)[(size_t)row * (N_EDGES / 4) + t];
        i0 = v.x; i1 = v.y; i2 = v.z; i3 = v.w;
    } else {
        const longlong2* p = (const longlong2*)((const long long*)ei + (size_t)row * N_EDGES);
        longlong2 a = p[2 * t];
        longlong2 b = p[2 * t + 1];
        i0 = (int)a.x; i1 = (int)a.y; i2 = (int)b.x; i3 = (int)b.y;
    }
}

__device__ __forceinline__ void load_idx2(const void* ei, int row, int t,
                                          int& i0, int& i1) {
    if (!g_idx64) {
        int2 v = ((const int2*)ei)[(size_t)row * (N_EDGES / 2) + t];
        i0 = v.x; i1 = v.y;
    } else {
        longlong2 v = ((const longlong2*)((const long long*)ei + (size_t)row * N_EDGES))[t];
        i0 = (int)v.x; i1 = (int)v.y;
    }
}

// ---------------------------------------------------------------- init: deg only (warms deg lines in L2)
__global__ void k_init() {
    int i = blockIdx.x * blockDim.x + threadIdx.x;
    if (i < N_NODES) g_deg[i] = 1.0f;
}

// ---------------------------------------------------------------- pass 1: degree (4 edges/thread)
__global__ void k_deg(const void* __restrict__ ei, const float4* __restrict__ ew4) {
    int t = blockIdx.x * blockDim.x + threadIdx.x;   // t < N_EDGES/4 exactly
    float4 w = ew4[t];
    int d0, d1, d2, d3;
    load_idx4(ei, 1, t, d0, d1, d2, d3);
    if ((unsigned)d0 < N_NODES) atomicAdd(&g_deg[d0], w.x);
    if ((unsigned)d1 < N_NODES) atomicAdd(&g_deg[d1], w.y);
    if ((unsigned)d2 < N_NODES) atomicAdd(&g_deg[d2], w.z);
    if ((unsigned)d3 < N_NODES) atomicAdd(&g_deg[d3], w.w);
}

// ---------------------------------------------------------------- node: dis, q (+ zero acc,u right before k_msgu needs them)
__global__ void k_dis(const float* __restrict__ x) {
    int i = blockIdx.x * blockDim.x + threadIdx.x;
    if (i < N_NODES) {
        float s = rsqrtf(g_deg[i]);     // deg >= 1 (self-loop weight 1, set by k_init)
        g_dis[i] = s;
        g_q[i]   = s * x[i];
        g_acc[i] = 0.0f;                // zero + L2-warm the scatter targets
        g_u[i]   = 0.0f;
    }
}

// ---------------------------------------------------------------- pass 2 (fused, 2 edges/thread, TB=512):
//   acc[d] += ew * q[s]        (layer-1 aggregation)
//   u[s]   += ew * dis[d]      (edge coefficient of final sum)
// 11 memops/thread — measured at the lane floor (R4/R11); 19 collapses (R5).
__global__ void k_msgu(const void* __restrict__ ei, const float2* __restrict__ ew2) {
    int t = blockIdx.x * blockDim.x + threadIdx.x;   // t < N_EDGES/2 exactly
    float2 w = ew2[t];
    int s0, s1, d0, d1;
    load_idx2(ei, 0, t, s0, s1);
    load_idx2(ei, 1, t, d0, d1);
    bool vs0 = (unsigned)s0 < N_NODES, vs1 = (unsigned)s1 < N_NODES;
    bool vd0 = (unsigned)d0 < N_NODES, vd1 = (unsigned)d1 < N_NODES;
    float q0 = vs0 ? g_q[s0]   : 0.0f;
    float q1 = vs1 ? g_q[s1]   : 0.0f;
    float c0 = vd0 ? g_dis[d0] : 0.0f;
    float c1 = vd1 ? g_dis[d1] : 0.0f;
    if (vd0) atomicAdd(&g_acc[d0], w.x * q0);
    if (vd1) atomicAdd(&g_acc[d1], w.y * q1);
    if (vs0) atomicAdd(&g_u[s0],   w.x * c0);
    if (vs1) atomicAdd(&g_u[s1],   w.y * c1);
}

// ---------------------------------------------------------------- shared-mem double tree reduce
__device__ __forceinline__ void block_reduce_store(float a0, float a1, int slot) {
    __shared__ double sm0[NODE_TB], sm1[NODE_TB];
    int t = threadIdx.x;
    sm0[t] = (double)a0;
    sm1[t] = (double)a1;
    __syncthreads();
    #pragma unroll
    for (int s = NODE_TB / 2; s > 0; s >>= 1) {
        if (t < s) { sm0[t] += sm0[t + s]; sm1[t] += sm1[t + s]; }
        __syncthreads();
    }
    if (t == 0) { g_part0[slot] = sm0[0]; g_part1[slot] = sm1[0]; }
}

// ---------------------------------------------------------------- node: MLP + full per-node contribution
// contribution of node i to s[c]:  h2[i,c] * (1/deg_i + dis_i * u_i)
__global__ void k_node(const float* __restrict__ x, const float* __restrict__ W1,
                       const float* __restrict__ b1, const float* __restrict__ W2) {
    __shared__ float sW1[16], sb1[16], sW2[32];
    int t = threadIdx.x;
    if (t < 16) { sW1[t] = W1[t]; sb1[t] = b1[t]; }
    if (t < 32) sW2[t] = W2[t];
    __syncthreads();

    float a0 = 0.0f, a1 = 0.0f;
    int stride = gridDim.x * blockDim.x;
    for (int i = blockIdx.x * blockDim.x + t; i < N_NODES; i += stride) {
        float dis = g_dis[i];
        float inv = dis * dis;                     // 1/deg
        float agg = dis * g_acc[i] + x[i] * inv;   // layer-1 scalar aggregate
        float h0 = 0.0f, h1 = 0.0f;
        #pragma unroll
        for (int j = 0; j < 16; j++) {
            float h = fmaxf(fmaf(sW1[j], agg, sb1[j]), 0.0f);
            h0 = fmaf(h, sW2[2 * j],     h0);
            h1 = fmaf(h, sW2[2 * j + 1], h1);
        }
        float coef = fmaf(dis, g_u[i], inv);       // self + edge terms of final sum
        a0 = fmaf(coef, h0, a0);
        a1 = fmaf(coef, h1, a1);
    }
    block_reduce_store(a0, a1, blockIdx.x);
}

// ---------------------------------------------------------------- final: reduce partials, bias, softmax
__global__ void k_final(const float* __restrict__ b2, float* __restrict__ out) {
    __shared__ double sm0[256], sm1[256];
    int t = threadIdx.x;
    double s0 = 0.0, s1 = 0.0;
    for (int k = t; k < NPART; k += 256) { s0 += g_part0[k]; s1 += g_part1[k]; }
    sm0[t] = s0; sm1[t] = s1;
    __syncthreads();
    #pragma unroll
    for (int s = 128; s > 0; s >>= 1) {
        if (t < s) { sm0[t] += sm0[t + s]; sm1[t] += sm1[t + s]; }
        __syncthreads();
    }
    if (t == 0) {
        double v0 = sm0[0] + (double)N_NODES * (double)b2[0];
        double v1 = sm1[0] + (double)N_NODES * (double)b2[1];
        double m  = fmax(v0, v1);
        double e0 = exp(v0 - m), e1 = exp(v1 - m);
        double den = e0 + e1;
        out[0] = (float)(e0 / den);
        out[1] = (float)(e1 / den);
    }
}

// ---------------------------------------------------------------- launch
extern "C" void kernel_launch(void* const* d_in, const int* in_sizes, int n_in,
                              void* d_out, int out_size) {
    const float* x  = (const float*)d_in[0];
    const void*  ei = d_in[1];                 // int32 OR int64, detected on device
    const float* ew = (const float*)d_in[2];
    const float* W1 = (const float*)d_in[3];
    const float* b1 = (const float*)d_in[4];
    const float* W2 = (const float*)d_in[5];
    const float* b2 = (const float*)d_in[6];

    const int TB = 256;
    const int nodeBlocks  = (N_NODES + TB - 1) / TB;        // 1954
    const int edge4Blocks = (N_EDGES / 4) / TB;             // 15625 exact
    const int edge2Blocks = (N_EDGES / 2) / 512;            // 15625 exact (TB=512)

    k_detect<<<1, 32>>>((const int*)ei);
    k_init  <<<nodeBlocks, TB>>>();
    k_deg   <<<edge4Blocks, TB>>>(ei, (const float4*)ew);
    k_dis   <<<nodeBlocks, TB>>>(x);
    k_msgu  <<<edge2Blocks, 512>>>(ei, (const float2*)ew);
    k_node  <<<NODE_GRID, NODE_TB>>>(x, W1, b1, W2);
    k_final <<<1, 256>>>(b2, (float*)d_out);
}